// round 12
// baseline (speedup 1.0000x reference)
#include <cuda_runtime.h>
#include <math.h>
#include <stdint.h>

// ---------------- problem constants ----------------
#define Bn 2
#define Hn 8
#define Ln 4096
#define Dm 512
#define dh 64
#define NBH (Bn*Hn)       // 16
#define SMAX 64           // upper bound on n_top (actual 45)
#define NCH 128           // cumsum chunks per bh (32 rows each)

// ---------------- device scratch (no allocs allowed) ----------------
__device__ __align__(256) float g_q[(size_t)NBH*Ln*dh];   // [bh][l][d]
__device__ __align__(256) float g_k[(size_t)NBH*Ln*dh];
__device__ __align__(256) float g_v[(size_t)NBH*Ln*dh];
__device__ __align__(256) float g_m[(size_t)NBH*Ln];
__device__ int   g_top[NBH*SMAX];
__device__ __align__(256) float g_tot[(size_t)NBH*NCH*dh]; // chunk totals for cumsum

// ---------------- f32x2 helpers (Blackwell packed fp32) ----------------
__device__ __forceinline__ unsigned long long dup_f32(float x){
    unsigned long long r;
    asm("mov.b64 %0, {%1, %1};" : "=l"(r) : "f"(x));
    return r;
}
__device__ __forceinline__ unsigned long long ffma2(unsigned long long a,
                                                    unsigned long long b,
                                                    unsigned long long c){
    unsigned long long d;
    asm("fma.rn.f32x2 %0, %1, %2, %3;" : "=l"(d) : "l"(a), "l"(b), "l"(c));
    return d;
}
__device__ __forceinline__ float2 unpack2(unsigned long long v){
    float2 r;
    asm("mov.b64 {%0, %1}, %2;" : "=f"(r.x), "=f"(r.y) : "l"(v));
    return r;
}

// ---------------- K1: fused fp32 FFMA2 projection GEMM ----------------
// z in {0,1,2} selects (X, W, bias, out) triple.
// B held in smem as pre-duplicated (b,b) 64-bit pairs, j-split layout:
// Bd[j][k][slot] = dup(W_tile[k][slot*8 + j])  -> compute reads LDS.64, 1 wavefront.
#define BM 128
#define BN 128
#define BK 16
#define PA 132   // padded A row stride (floats)
#define A_STG (BK*PA)                 // floats per A stage
#define B_STG (8*BK*16)               // ull per B stage
#define SMEMB (2*A_STG*4 + 2*B_STG*8) // 16896 + 32768 = 49664 bytes

__global__ __launch_bounds__(256, 2)
void proj_fused(const float* __restrict__ Xq, const float* __restrict__ Xk,
                const float* __restrict__ Xv,
                const float* __restrict__ Wq, const float* __restrict__ Wk,
                const float* __restrict__ Wv,
                const float* __restrict__ bq, const float* __restrict__ bk_,
                const float* __restrict__ bv,
                float* __restrict__ oq, float* __restrict__ ok,
                float* __restrict__ ov)
{
    extern __shared__ __align__(16) char smraw[];
    float* As = (float*)smraw;                         // [2][BK][PA]
    unsigned long long* Bd = (unsigned long long*)(smraw + 2*A_STG*4); // [2][8][BK][16]

    const int z = blockIdx.z;
    const float* X    = (z == 0) ? Xq : (z == 1) ? Xk : Xv;
    const float* W    = (z == 0) ? Wq : (z == 1) ? Wk : Wv;
    const float* bias = (z == 0) ? bq : (z == 1) ? bk_ : bv;
    float*       out  = (z == 0) ? oq : (z == 1) ? ok : ov;

    const int tid = threadIdx.x;
    const int tx = tid & 15, ty = tid >> 4;
    const int m0 = ty * 8;
    const int rowBase = blockIdx.y * BM;
    const int colBase = blockIdx.x * BN;

    // per-thread gmem load coords
    const int a_r  = tid >> 2;          // + t*64  -> row in tile [0,128)
    const int a_kq = (tid & 3) * 4;     // k quad
    const int b_r  = tid >> 5;          // + t*8   -> k row [0,16)
    const int b_cq = (tid & 31) * 4;    // col quad (multiple of 4)
    const int b_slot  = b_cq >> 3;      // [0,16)
    const int b_jbase = b_cq & 7;       // 0 or 4

    float4 a_stg[2], b_stg[2];

    // ---- prologue: load + store chunk 0 into stage 0 ----
    #pragma unroll
    for (int t = 0; t < 2; t++) {
        a_stg[t] = *(const float4*)(X + (size_t)(rowBase + a_r + t*64) * Dm + a_kq);
        b_stg[t] = *(const float4*)(W + (size_t)(b_r + t*8) * Dm + colBase + b_cq);
    }
    #pragma unroll
    for (int t = 0; t < 2; t++) {
        As[(a_kq + 0)*PA + a_r + t*64] = a_stg[t].x;
        As[(a_kq + 1)*PA + a_r + t*64] = a_stg[t].y;
        As[(a_kq + 2)*PA + a_r + t*64] = a_stg[t].z;
        As[(a_kq + 3)*PA + a_r + t*64] = a_stg[t].w;
        int kk = b_r + t*8;
        Bd[(b_jbase + 0)*(BK*16) + kk*16 + b_slot] = dup_f32(b_stg[t].x);
        Bd[(b_jbase + 1)*(BK*16) + kk*16 + b_slot] = dup_f32(b_stg[t].y);
        Bd[(b_jbase + 2)*(BK*16) + kk*16 + b_slot] = dup_f32(b_stg[t].z);
        Bd[(b_jbase + 3)*(BK*16) + kk*16 + b_slot] = dup_f32(b_stg[t].w);
    }
    __syncthreads();

    unsigned long long acc[4][8];
    #pragma unroll
    for (int i = 0; i < 4; i++)
        #pragma unroll
        for (int j = 0; j < 8; j++) acc[i][j] = 0ull;

    int s = 0;
    for (int kc = 0; kc < Dm; kc += BK) {
        const bool more = (kc + BK < Dm);
        if (more) {
            #pragma unroll
            for (int t = 0; t < 2; t++) {
                a_stg[t] = *(const float4*)(X + (size_t)(rowBase + a_r + t*64) * Dm + (kc + BK) + a_kq);
                b_stg[t] = *(const float4*)(W + (size_t)(kc + BK + b_r + t*8) * Dm + colBase + b_cq);
            }
        }

        const float* Acur = As + s * A_STG;
        const unsigned long long* Bcur = Bd + s * B_STG;

        #pragma unroll
        for (int k = 0; k < BK; k++) {
            ulonglong2 a01 = *(const ulonglong2*)(Acur + k*PA + m0);
            ulonglong2 a23 = *(const ulonglong2*)(Acur + k*PA + m0 + 4);
            unsigned long long ap[4] = { a01.x, a01.y, a23.x, a23.y };
            unsigned long long bd[8];
            #pragma unroll
            for (int j = 0; j < 8; j++)
                bd[j] = Bcur[j*(BK*16) + k*16 + tx];
            #pragma unroll
            for (int i = 0; i < 4; i++)
                #pragma unroll
                for (int j = 0; j < 8; j++)
                    acc[i][j] = ffma2(ap[i], bd[j], acc[i][j]);
        }

        if (more) {
            const int so = s ^ 1;
            float* Anx = As + so * A_STG;
            unsigned long long* Bnx = Bd + so * B_STG;
            #pragma unroll
            for (int t = 0; t < 2; t++) {
                Anx[(a_kq + 0)*PA + a_r + t*64] = a_stg[t].x;
                Anx[(a_kq + 1)*PA + a_r + t*64] = a_stg[t].y;
                Anx[(a_kq + 2)*PA + a_r + t*64] = a_stg[t].z;
                Anx[(a_kq + 3)*PA + a_r + t*64] = a_stg[t].w;
                int kk = b_r + t*8;
                Bnx[(b_jbase + 0)*(BK*16) + kk*16 + b_slot] = dup_f32(b_stg[t].x);
                Bnx[(b_jbase + 1)*(BK*16) + kk*16 + b_slot] = dup_f32(b_stg[t].y);
                Bnx[(b_jbase + 2)*(BK*16) + kk*16 + b_slot] = dup_f32(b_stg[t].z);
                Bnx[(b_jbase + 3)*(BK*16) + kk*16 + b_slot] = dup_f32(b_stg[t].w);
            }
            __syncthreads();
        }
        s ^= 1;
    }

    // ---- epilogue: add bias, scatter to [bh][l][d] layout ----
    // thread's 8 columns are colBase + tx*8 + j  (j = 0..7)
    const int n0 = tx * 8;
    float bvv[8];
    #pragma unroll
    for (int j = 0; j < 8; j++) bvv[j] = bias[colBase + n0 + j];

    const int c0 = colBase + n0;
    const int h = c0 >> 6;
    const int d0 = c0 & 63;

    #pragma unroll
    for (int i = 0; i < 4; i++) {
        #pragma unroll
        for (int rr = 0; rr < 2; rr++) {
            int r = rowBase + m0 + 2 * i + rr;
            int b = r >> 12;
            int l = r & (Ln - 1);
            float* o = out + (((size_t)(b * Hn + h) * Ln + l) << 6) + d0;
            float vals[8];
            #pragma unroll
            for (int j = 0; j < 8; j++) {
                float2 f2 = unpack2(acc[i][j]);
                vals[j] = (rr == 0 ? f2.x : f2.y) + bvv[j];
            }
            *(float4*)o       = make_float4(vals[0], vals[1], vals[2], vals[3]);
            *(float4*)(o + 4) = make_float4(vals[4], vals[5], vals[6], vals[7]);
        }
    }
}

// ---------------- K2: sampled scores -> m ----------------
__global__ __launch_bounds__(256)
void sample_score_kernel(const int* __restrict__ idxs, int S)
{
    int gid = blockIdx.x * 8 + (threadIdx.x >> 5);
    int lane = threadIdx.x & 31;
    int bh = gid >> 12;
    int l = gid & (Ln - 1);

    const float* q = g_q + ((size_t)bh << 18) + ((size_t)l << 6);
    float2 q2 = *(const float2*)(q + 2 * lane);
    const float* kb = g_k + ((size_t)bh << 18);

    float mx = -INFINITY, sm = 0.f;
    for (int s = 0; s < S; s++) {
        int idx = idxs[l * S + s];
        float2 k2 = *(const float2*)(kb + ((size_t)idx << 6) + 2 * lane);
        float p = q2.x * k2.x + q2.y * k2.y;
        #pragma unroll
        for (int o = 16; o; o >>= 1) p += __shfl_xor_sync(0xffffffffu, p, o);
        mx = fmaxf(mx, p);
        sm += p;
    }
    if (lane == 0)
        g_m[((size_t)bh << 12) + l] = mx - sm * (1.0f / (float)Ln);
}

// ---------------- K3: top-S argmax passes per (b,h) ----------------
__global__ __launch_bounds__(256)
void topk_kernel(int S)
{
    __shared__ float sm[Ln];
    __shared__ float rv[256];
    __shared__ int   ri[256];
    int bh = blockIdx.x, tid = threadIdx.x;

    for (int i = tid; i < Ln; i += 256) sm[i] = g_m[((size_t)bh << 12) + i];
    __syncthreads();

    for (int t = 0; t < S; t++) {
        float best = -INFINITY;
        int bi = Ln;
        for (int i = tid; i < Ln; i += 256) {
            float v = sm[i];
            if (v > best || (v == best && i < bi)) { best = v; bi = i; }
        }
        rv[tid] = best; ri[tid] = bi;
        __syncthreads();
        for (int o = 128; o; o >>= 1) {
            if (tid < o) {
                if (rv[tid + o] > rv[tid] ||
                    (rv[tid + o] == rv[tid] && ri[tid + o] < ri[tid])) {
                    rv[tid] = rv[tid + o]; ri[tid] = ri[tid + o];
                }
            }
            __syncthreads();
        }
        if (tid == 0) {
            g_top[bh * SMAX + t] = ri[0];
            sm[ri[0]] = -INFINITY;
        }
        __syncthreads();
    }
}

// ---------------- K5a: 32-row chunk-local cumsum of v (float4) ----------------
__global__ __launch_bounds__(128)
void cumsum_part(float* __restrict__ out)
{
    int tid = threadIdx.x;
    int c = blockIdx.x * 8 + (tid >> 4);   // chunk [0,128)
    int bh = blockIdx.y;
    int d4 = (tid & 15) * 4;
    int b = bh >> 3, h = bh & 7;
    const float* vb = g_v + ((size_t)bh << 18) + ((size_t)(c * 32) << 6) + d4;
    float* ob = out + ((size_t)(b * Ln + c * 32)) * Dm + h * 64 + d4;
    float4 run = make_float4(0.f, 0.f, 0.f, 0.f);
    #pragma unroll 8
    for (int i = 0; i < 32; i++) {
        float4 v = *(const float4*)(vb + ((size_t)i << 6));
        run.x += v.x; run.y += v.y; run.z += v.z; run.w += v.w;
        *(float4*)(ob + (size_t)i * Dm) = run;
    }
    *(float4*)&g_tot[((size_t)bh * NCH + c) * 64 + d4] = run;
}

// ---------------- K5b: Kogge-Stone inclusive scan of chunk totals ----------------
__global__ __launch_bounds__(256)
void cumsum_scan_ks()
{
    __shared__ float S[NCH * 64];   // 32 KB
    int bh = blockIdx.x, tid = threadIdx.x;
    float* gt = g_tot + (size_t)bh * (NCH * 64);

    for (int i = tid; i < NCH * 64; i += 256) S[i] = gt[i];
    __syncthreads();

    for (int off = 1; off < NCH; off <<= 1) {
        float t[32];
        #pragma unroll
        for (int j = 0; j < 32; j++) {
            int idx = tid + j * 256;
            int c = idx >> 6;
            t[j] = (c >= off) ? S[idx - (off << 6)] : 0.f;
        }
        __syncthreads();
        #pragma unroll
        for (int j = 0; j < 32; j++) S[tid + j * 256] += t[j];
        __syncthreads();
    }

    for (int i = tid; i < NCH * 64; i += 256) gt[i] = S[i];
}

// ---------------- K5c: add chunk offsets (inclusive prefix of c-1) ----------------
__global__ __launch_bounds__(128)
void cumsum_add(float* __restrict__ out)
{
    int tid = threadIdx.x;
    int c = blockIdx.x * 8 + (tid >> 4);
    if (c == 0) return;
    int bh = blockIdx.y;
    int d4 = (tid & 15) * 4;
    float4 off = *(const float4*)&g_tot[((size_t)bh * NCH + (c - 1)) * 64 + d4];
    int b = bh >> 3, h = bh & 7;
    float* ob = out + ((size_t)(b * Ln + c * 32)) * Dm + h * 64 + d4;
    #pragma unroll 8
    for (int i = 0; i < 32; i++) {
        float4 v = *(const float4*)(ob + (size_t)i * Dm);
        v.x += off.x; v.y += off.y; v.z += off.z; v.w += off.w;
        *(float4*)(ob + (size_t)i * Dm) = v;
    }
}

// ---------------- K4: full attention on selected rows + scatter ----------------
__global__ __launch_bounds__(256)
void attn_kernel(float* __restrict__ out, int S)
{
    __shared__ float qs[64];
    __shared__ float sc[Ln];
    __shared__ float red[256];
    __shared__ float vr[4][64];

    int bh = blockIdx.y, u = blockIdx.x;
    int tid = threadIdx.x;
    int lu = g_top[bh * SMAX + u];
    int nk = lu + 1;   // causal: keys 0..lu inclusive

    const float* qb = g_q + ((size_t)bh << 18) + ((size_t)lu << 6);
    if (tid < 64) qs[tid] = qb[tid];
    __syncthreads();

    int warp = tid >> 5, lane = tid & 31;
    const float* kb = g_k + ((size_t)bh << 18);
    float q0 = qs[2 * lane], q1 = qs[2 * lane + 1];
    const float scale = 0.125f;  // 1/sqrt(64)

    for (int key = warp; key < nk; key += 8) {
        float2 k2 = *(const float2*)(kb + ((size_t)key << 6) + 2 * lane);
        float p = q0 * k2.x + q1 * k2.y;
        #pragma unroll
        for (int o = 16; o; o >>= 1) p += __shfl_xor_sync(0xffffffffu, p, o);
        if (lane == 0) sc[key] = p * scale;
    }
    __syncthreads();

    float mx = -INFINITY;
    for (int i = tid; i < nk; i += 256) mx = fmaxf(mx, sc[i]);
    red[tid] = mx; __syncthreads();
    for (int o = 128; o; o >>= 1) {
        if (tid < o) red[tid] = fmaxf(red[tid], red[tid + o]);
        __syncthreads();
    }
    mx = red[0]; __syncthreads();

    float z = 0.f;
    for (int i = tid; i < nk; i += 256) {
        float e = __expf(sc[i] - mx);
        sc[i] = e;
        z += e;
    }
    red[tid] = z; __syncthreads();
    for (int o = 128; o; o >>= 1) {
        if (tid < o) red[tid] += red[tid + o];
        __syncthreads();
    }
    z = red[0]; __syncthreads();

    int g = tid >> 6, dl = tid & 63;
    const float* vb = g_v + ((size_t)bh << 18);
    float acc = 0.f;
    for (int key = g; key < nk; key += 4)
        acc += sc[key] * vb[((size_t)key << 6) + dl];
    vr[g][dl] = acc;
    __syncthreads();

    if (tid < 64) {
        float s = (vr[0][tid] + vr[1][tid]) + (vr[2][tid] + vr[3][tid]);
        int b = bh >> 3, h = bh & 7;
        out[((size_t)(b * Ln + lu)) * Dm + h * 64 + tid] = s / z;
    }
}

// ---------------- launch ----------------
extern "C" void kernel_launch(void* const* d_in, const int* in_sizes, int n_in,
                              void* d_out, int out_size)
{
    const float* queries = (const float*)d_in[0];
    const float* keys    = (const float*)d_in[1];
    const float* values  = (const float*)d_in[2];
    const float* Wq = (const float*)d_in[3];
    const float* bq = (const float*)d_in[4];
    const float* Wk = (const float*)d_in[5];
    const float* bk = (const float*)d_in[6];
    const float* Wv = (const float*)d_in[7];
    const float* bv = (const float*)d_in[8];
    const int*  idxs = (const int*)d_in[9];
    int S = in_sizes[9] / Ln;   // 45
    float* out = (float*)d_out;

    float *gq, *gk, *gv;
    cudaGetSymbolAddress((void**)&gq, g_q);
    cudaGetSymbolAddress((void**)&gk, g_k);
    cudaGetSymbolAddress((void**)&gv, g_v);

    cudaFuncSetAttribute(proj_fused, cudaFuncAttributeMaxDynamicSharedMemorySize,
                         SMEMB);

    dim3 gemmGrid(Dm / BN, (Bn * Ln) / BM, 3);   // (4, 64, 3)
    proj_fused<<<gemmGrid, 256, SMEMB>>>(queries, keys, values,
                                         Wq, Wk, Wv, bq, bk, bv,
                                         gq, gk, gv);

    // cumsum of v into out (final layout)
    cumsum_part<<<dim3(16, NBH), 128>>>(out);
    cumsum_scan_ks<<<NBH, 256>>>();
    cumsum_add<<<dim3(16, NBH), 128>>>(out);

    // sparse-attention measurement + selection
    sample_score_kernel<<<(NBH * Ln) / 8, 256>>>(idxs, S);
    topk_kernel<<<NBH, 256>>>(S);

    // full attention on selected rows, scatter into out
    attn_kernel<<<dim3(S, NBH), 256>>>(out, S);
}